// round 6
// baseline (speedup 1.0000x reference)
#include <cuda_runtime.h>
#include <cuda_bf16.h>
#include <math.h>
#include <stdint.h>

#define N_NODES 50000
#define N_EDGES 500000
#define D 128
#define BN_EPS 1e-5f

// ---------------- scratch (static device globals; no allocation) ----------------
__device__ float g_P[(size_t)N_NODES * 512];     // [PF1|PF2|PS1|PS2] per node
__device__ float g_agg[(size_t)N_NODES * D];     // scatter-sum target
__device__ float g_B1[128 * 512];                // repacked node weights (fp32)
__device__ float g_stats[2 * D];                 // [sum | sumsq]
// B fragments for mma.sync m16n8k16 (bf16), fragment-linear:
// index = ((((term*8 + kstep)*32 + ntile)*32) + lane)*2 + reg   (uint32 slots)
// term 0 = hi, term 1 = lo. B logical: [k=128][n=256], n=2c -> Wf[256+k][c], n=2c+1 -> Ws[256+k][c]
__device__ __align__(16) uint32_t g_Bfrag[2 * 8 * 32 * 32 * 2];

// ---------------- weight repack ----------------
__global__ void prep_weights(const float* __restrict__ Wf, const float* __restrict__ Ws) {
    int i = blockIdx.x * blockDim.x + threadIdx.x;
    if (i < 128 * 512) {
        int k = i >> 9, j = i & 511;
        float v;
        if (j < 128)      v = Wf[k * 128 + j];
        else if (j < 256) v = Wf[(128 + k) * 128 + (j - 128)];
        else if (j < 384) v = Ws[k * 128 + (j - 256)];
        else              v = Ws[(128 + k) * 128 + (j - 384)];
        g_B1[i] = v;
    }
    if (i < 32768) {
        int reg   = i & 1;
        int lane  = (i >> 1) & 31;
        int ntile = (i >> 6) & 31;
        int kstep = (i >> 11) & 7;
        int term  = (i >> 14) & 1;
        int k0 = kstep * 16 + (lane & 3) * 2 + reg * 8;
        int n  = ntile * 8 + (lane >> 2);
        int c  = n >> 1;
        const float* W = (n & 1) ? Ws : Wf;
        float v0 = W[(256 + k0) * 128 + c];
        float v1 = W[(256 + k0 + 1) * 128 + c];
        __nv_bfloat16 h0 = __float2bfloat16_rn(v0);
        __nv_bfloat16 h1 = __float2bfloat16_rn(v1);
        uint32_t out;
        if (term == 0) {
            out = (uint32_t)__bfloat16_as_ushort(h0) | ((uint32_t)__bfloat16_as_ushort(h1) << 16);
        } else {
            __nv_bfloat16 l0 = __float2bfloat16_rn(v0 - __bfloat162float(h0));
            __nv_bfloat16 l1 = __float2bfloat16_rn(v1 - __bfloat162float(h1));
            out = (uint32_t)__bfloat16_as_ushort(l0) | ((uint32_t)__bfloat16_as_ushort(l1) << 16);
        }
        g_Bfrag[i] = out;
    }
}

// ---------------- zero scratch ----------------
__global__ void zero_scratch() {
    size_t n4 = (size_t)N_NODES * D / 4;
    float4* p = reinterpret_cast<float4*>(g_agg);
    for (size_t i = blockIdx.x * blockDim.x + threadIdx.x; i < n4; i += (size_t)gridDim.x * blockDim.x)
        p[i] = make_float4(0.f, 0.f, 0.f, 0.f);
    int t = blockIdx.x * blockDim.x + threadIdx.x;
    if (t < 2 * D) g_stats[t] = 0.f;
}

// ---------------- node SGEMM: g_P[M,512] = x[M,128] @ g_B1[128,512] ----------------
#define BM 64
#define BN 64
#define BK 16
__global__ __launch_bounds__(256) void node_gemm(const float* __restrict__ A, int M)
{
    const float* __restrict__ B = g_B1;
    float* __restrict__ C = g_P;
    const int N = 512;
    __shared__ float As[BK][BM];
    __shared__ float Bs[BK][BN];
    const int tid = threadIdx.x;
    const int row0 = blockIdx.y * BM;
    const int col0 = blockIdx.x * BN;
    const int tr = tid >> 4, tc = tid & 15;
    const int a_r = tid >> 2, a_c4 = (tid & 3) * 4;
    const int b_r = tid >> 4, b_c4 = (tid & 15) * 4;
    float acc[4][4];
#pragma unroll
    for (int i = 0; i < 4; i++)
#pragma unroll
        for (int j = 0; j < 4; j++) acc[i][j] = 0.f;
    const int ar = row0 + a_r;
    for (int k0 = 0; k0 < 128; k0 += BK) {
        float4 av = make_float4(0.f, 0.f, 0.f, 0.f);
        if (ar < M) av = *reinterpret_cast<const float4*>(A + (size_t)ar * 128 + k0 + a_c4);
        As[a_c4 + 0][a_r] = av.x; As[a_c4 + 1][a_r] = av.y;
        As[a_c4 + 2][a_r] = av.z; As[a_c4 + 3][a_r] = av.w;
        float4 bv = *reinterpret_cast<const float4*>(B + (size_t)(k0 + b_r) * N + col0 + b_c4);
        *reinterpret_cast<float4*>(&Bs[b_r][b_c4]) = bv;
        __syncthreads();
#pragma unroll
        for (int k = 0; k < BK; k++) {
            float4 a = *reinterpret_cast<float4*>(&As[k][tr * 4]);
            float4 b = *reinterpret_cast<float4*>(&Bs[k][tc * 4]);
            acc[0][0] += a.x * b.x; acc[0][1] += a.x * b.y; acc[0][2] += a.x * b.z; acc[0][3] += a.x * b.w;
            acc[1][0] += a.y * b.x; acc[1][1] += a.y * b.y; acc[1][2] += a.y * b.z; acc[1][3] += a.y * b.w;
            acc[2][0] += a.z * b.x; acc[2][1] += a.z * b.y; acc[2][2] += a.z * b.z; acc[2][3] += a.z * b.w;
            acc[3][0] += a.w * b.x; acc[3][1] += a.w * b.y; acc[3][2] += a.w * b.z; acc[3][3] += a.w * b.w;
        }
        __syncthreads();
    }
#pragma unroll
    for (int i = 0; i < 4; i++) {
        int row = row0 + tr * 4 + i;
        if (row < M) {
            float4 v = make_float4(acc[i][0], acc[i][1], acc[i][2], acc[i][3]);
            *reinterpret_cast<float4*>(C + (size_t)row * N + col0 + tc * 4) = v;
        }
    }
}

// ---------------- activations ----------------
__device__ __forceinline__ float sigmoidf_(float x) { return 1.f / (1.f + expf(-x)); }
__device__ __forceinline__ float softplusf_(float x) {
    return fmaxf(x, 0.f) + log1pf(expf(-fabsf(x)));
}

__device__ __forceinline__ void mma_bf16(float* d, uint32_t a0, uint32_t a1, uint32_t a2,
                                         uint32_t a3, uint32_t b0, uint32_t b1) {
    asm volatile(
        "mma.sync.aligned.m16n8k16.row.col.f32.bf16.bf16.f32 "
        "{%0,%1,%2,%3}, {%4,%5,%6,%7}, {%8,%9}, {%0,%1,%2,%3};"
        : "+f"(d[0]), "+f"(d[1]), "+f"(d[2]), "+f"(d[3])
        : "r"(a0), "r"(a1), "r"(a2), "r"(a3), "r"(b0), "r"(b1));
}

// ---------------- fused edge GEMM (mma.sync bf16-split) + gate + scatter ----------------
// CTA: 64 edges x 256 interleaved cols (2c=f_c, 2c+1=s_c), K=128.
// smem: [0,256) src, [256,512) tgt, union at 512: { Ahi 64x272B, Alo 64x272B } / { D 64x260 fp32 }
#define SM_SRC 0
#define SM_TGT 256
#define SM_AHI 512
#define SM_ALO (512 + 64 * 272)
#define SM_D   512
#define DSTRIDE 260
#define EDGE_SMEM (512 + 64 * DSTRIDE * 4 + 1024)

__global__ __launch_bounds__(256, 2) void edge_fused_mma(
    const float* __restrict__ A,
    const int* __restrict__ src, const int* __restrict__ tgt,
    const float* __restrict__ bf, const float* __restrict__ bs)
{
    extern __shared__ char basep[];
    const int tid = threadIdx.x;
    const int wid = tid >> 5;
    const int lane = tid & 31;
    const int row0 = blockIdx.x * 64;
    const int warpM = wid & 1;   // 0..1 (32 rows each)
    const int warpN = wid >> 1;  // 0..3 (64 interleaved cols each)

    int* s_src = reinterpret_cast<int*>(basep + SM_SRC);
    int* s_tgt = reinterpret_cast<int*>(basep + SM_TGT);
    if (tid < 64) {
        int r = row0 + tid;
        s_src[tid] = (r < N_EDGES) ? src[r] : 0;
        s_tgt[tid] = (r < N_EDGES) ? tgt[r] : 0;
    }

    // A tile: load 64x128 fp32, split bf16 hi/lo into smem (row stride 272 B)
    {
        char* ahi = basep + SM_AHI;
        char* alo = basep + SM_ALO;
#pragma unroll
        for (int it = 0; it < 8; it++) {
            int lin = it * 256 + tid;        // float4 over 64x32
            int row = lin >> 5;
            int c4 = (lin & 31) << 2;
            int e = row0 + row;
            float4 v = make_float4(0.f, 0.f, 0.f, 0.f);
            if (e < N_EDGES) v = *reinterpret_cast<const float4*>(A + (size_t)e * 128 + c4);
            __nv_bfloat16 h0 = __float2bfloat16_rn(v.x), h1 = __float2bfloat16_rn(v.y);
            __nv_bfloat16 h2 = __float2bfloat16_rn(v.z), h3 = __float2bfloat16_rn(v.w);
            __nv_bfloat16 l0 = __float2bfloat16_rn(v.x - __bfloat162float(h0));
            __nv_bfloat16 l1 = __float2bfloat16_rn(v.y - __bfloat162float(h1));
            __nv_bfloat16 l2 = __float2bfloat16_rn(v.z - __bfloat162float(h2));
            __nv_bfloat16 l3 = __float2bfloat16_rn(v.w - __bfloat162float(h3));
            uint2 hp, lp;
            hp.x = (uint32_t)__bfloat16_as_ushort(h0) | ((uint32_t)__bfloat16_as_ushort(h1) << 16);
            hp.y = (uint32_t)__bfloat16_as_ushort(h2) | ((uint32_t)__bfloat16_as_ushort(h3) << 16);
            lp.x = (uint32_t)__bfloat16_as_ushort(l0) | ((uint32_t)__bfloat16_as_ushort(l1) << 16);
            lp.y = (uint32_t)__bfloat16_as_ushort(l2) | ((uint32_t)__bfloat16_as_ushort(l3) << 16);
            int off = row * 272 + c4 * 2;
            *reinterpret_cast<uint2*>(ahi + off) = hp;
            *reinterpret_cast<uint2*>(alo + off) = lp;
        }
    }
    __syncthreads();

    float acc[2][8][4];
#pragma unroll
    for (int mt = 0; mt < 2; mt++)
#pragma unroll
        for (int nt = 0; nt < 8; nt++)
#pragma unroll
            for (int j = 0; j < 4; j++) acc[mt][nt][j] = 0.f;

    // 3 terms: (Ahi,Bhi), (Alo,Bhi), (Ahi,Blo)
#pragma unroll
    for (int term = 0; term < 3; term++) {
        const char* Areg = basep + ((term == 1) ? SM_ALO : SM_AHI);
        const int bterm = (term == 2) ? 1 : 0;
#pragma unroll
        for (int kstep = 0; kstep < 8; kstep++) {
            uint2 bfr[8];
            const uint2* bp = reinterpret_cast<const uint2*>(g_Bfrag)
                              + (((bterm * 8 + kstep) * 32 + warpN * 8) * 32 + lane);
#pragma unroll
            for (int nt = 0; nt < 8; nt++) bfr[nt] = bp[nt * 32];
#pragma unroll
            for (int mt = 0; mt < 2; mt++) {
                int arow = warpM * 32 + mt * 16 + (lane >> 2);
                int acol = kstep * 16 + (lane & 3) * 2;
                const char* ap = Areg + arow * 272 + acol * 2;
                uint32_t a0 = *reinterpret_cast<const uint32_t*>(ap);
                uint32_t a1 = *reinterpret_cast<const uint32_t*>(ap + 8 * 272);
                uint32_t a2 = *reinterpret_cast<const uint32_t*>(ap + 16);
                uint32_t a3 = *reinterpret_cast<const uint32_t*>(ap + 8 * 272 + 16);
#pragma unroll
                for (int nt = 0; nt < 8; nt++)
                    mma_bf16(acc[mt][nt], a0, a1, a2, a3, bfr[nt].x, bfr[nt].y);
            }
        }
    }
    __syncthreads();   // A region dead; reuse as D staging

    // acc -> smem D [64][DSTRIDE]
    {
        float* Dsm = reinterpret_cast<float*>(basep + SM_D);
#pragma unroll
        for (int mt = 0; mt < 2; mt++) {
            int row = warpM * 32 + mt * 16 + (lane >> 2);
#pragma unroll
            for (int nt = 0; nt < 8; nt++) {
                int col = warpN * 64 + nt * 8 + (lane & 3) * 2;
                float* p0 = Dsm + (size_t)row * DSTRIDE + col;
                p0[0] = acc[mt][nt][0];
                p0[1] = acc[mt][nt][1];
                float* p1 = p0 + 8 * DSTRIDE;
                p1[0] = acc[mt][nt][2];
                p1[1] = acc[mt][nt][3];
            }
        }
    }
    __syncthreads();

    // epilogue: gate + scatter
    {
        const float* Dsm = reinterpret_cast<const float*>(basep + SM_D);
        const int tr = tid >> 5;   // 8 groups x 8 rows
        const int tc = tid & 31;   // orig cols tc*4..+3
        const float4 bfv = *reinterpret_cast<const float4*>(bf + tc * 4);
        const float4 bsv = *reinterpret_cast<const float4*>(bs + tc * 4);
#pragma unroll 4
        for (int i = 0; i < 8; i++) {
            int lr = tr * 8 + i;
            int e = row0 + lr;
            if (e >= N_EDGES) break;
            int sN = s_src[lr];
            int tN = s_tgt[lr];
            const float* dp = Dsm + (size_t)lr * DSTRIDE + tc * 8;
            float4 d0 = *reinterpret_cast<const float4*>(dp);       // f0,s0,f1,s1
            float4 d1 = *reinterpret_cast<const float4*>(dp + 4);   // f2,s2,f3,s3

            const float4 pf1 = *reinterpret_cast<const float4*>(g_P + (size_t)sN * 512 + 0   + tc * 4);
            const float4 pf2 = *reinterpret_cast<const float4*>(g_P + (size_t)tN * 512 + 128 + tc * 4);
            const float4 ps1 = *reinterpret_cast<const float4*>(g_P + (size_t)sN * 512 + 256 + tc * 4);
            const float4 ps2 = *reinterpret_cast<const float4*>(g_P + (size_t)tN * 512 + 384 + tc * 4);

            float f0 = d0.x + pf1.x + pf2.x + bfv.x;
            float s0 = d0.y + ps1.x + ps2.x + bsv.x;
            float f1 = d0.z + pf1.y + pf2.y + bfv.y;
            float s1 = d0.w + ps1.y + ps2.y + bsv.y;
            float f2 = d1.x + pf1.z + pf2.z + bfv.z;
            float s2 = d1.y + ps1.z + ps2.z + bsv.z;
            float f3 = d1.z + pf1.w + pf2.w + bfv.w;
            float s3 = d1.w + ps1.w + ps2.w + bsv.w;

            float m0 = sigmoidf_(f0) * softplusf_(s0);
            float m1 = sigmoidf_(f1) * softplusf_(s1);
            float m2 = sigmoidf_(f2) * softplusf_(s2);
            float m3 = sigmoidf_(f3) * softplusf_(s3);

            float* dst = g_agg + (size_t)sN * D + tc * 4;
            asm volatile("red.global.add.v4.f32 [%0], {%1, %2, %3, %4};"
                         :: "l"(dst), "f"(m0), "f"(m1), "f"(m2), "f"(m3) : "memory");
        }
    }
}

// ---------------- BN stats ----------------
__global__ __launch_bounds__(128) void bn_stats() {
    const int d = threadIdx.x;
    float sum = 0.f, sq = 0.f;
    for (int n = blockIdx.x; n < N_NODES; n += gridDim.x) {
        float v = g_agg[(size_t)n * D + d];
        sum += v;
        sq += v * v;
    }
    atomicAdd(&g_stats[d], sum);
    atomicAdd(&g_stats[D + d], sq);
}

// ---------------- BN apply + residual + softplus ----------------
__global__ __launch_bounds__(256) void final_kernel(
    const float* __restrict__ x, const float* __restrict__ gamma,
    const float* __restrict__ beta, float* __restrict__ out)
{
    const float invN = 1.0f / (float)N_NODES;
    for (size_t idx = (size_t)blockIdx.x * blockDim.x + threadIdx.x;
         idx < (size_t)N_NODES * D;
         idx += (size_t)gridDim.x * blockDim.x) {
        int d = (int)(idx & (D - 1));
        float mean = g_stats[d] * invN;
        float var = g_stats[D + d] * invN - mean * mean;
        float rstd = rsqrtf(var + BN_EPS);
        float a = (g_agg[idx] - mean) * rstd * gamma[d] + beta[d];
        out[idx] = softplusf_(x[idx] + a);
    }
}

// ---------------- launch ----------------
extern "C" void kernel_launch(void* const* d_in, const int* in_sizes, int n_in,
                              void* d_out, int out_size) {
    const float* x         = (const float*)d_in[0];
    const float* edge_attr = (const float*)d_in[1];
    const int*   edge_src  = (const int*)d_in[2];
    const int*   edge_tgt  = (const int*)d_in[3];
    const float* Wf        = (const float*)d_in[4];
    const float* bf        = (const float*)d_in[5];
    const float* Ws        = (const float*)d_in[6];
    const float* bs        = (const float*)d_in[7];
    const float* gamma     = (const float*)d_in[8];
    const float* beta      = (const float*)d_in[9];
    float* out = (float*)d_out;

    static bool attr_set = false;
    if (!attr_set) {
        cudaFuncSetAttribute(edge_fused_mma, cudaFuncAttributeMaxDynamicSharedMemorySize, EDGE_SMEM);
        attr_set = true;
    }

    prep_weights<<<256, 256>>>(Wf, Ws);
    zero_scratch<<<4096, 256>>>();
    {
        dim3 grid(512 / BN, (N_NODES + BM - 1) / BM);
        node_gemm<<<grid, 256>>>(x, N_NODES);
    }
    {
        int blocks = (N_EDGES + 63) / 64;
        edge_fused_mma<<<blocks, 256, EDGE_SMEM>>>(edge_attr, edge_src, edge_tgt, bf, bs);
    }
    bn_stats<<<512, 128>>>();
    final_kernel<<<(N_NODES * D + 255) / 256, 256>>>(x, gamma, beta, out);
}

// round 7
// speedup vs baseline: 1.9059x; 1.9059x over previous
#include <cuda_runtime.h>
#include <cuda_bf16.h>
#include <math.h>
#include <stdint.h>

#define N_NODES 50000
#define N_EDGES 500000
#define D 128
#define BN_EPS 1e-5f

// ---------------- scratch (static device globals; no allocation) ----------------
__device__ float g_P[(size_t)N_NODES * 512];     // [PF1|PF2|PS1|PS2] per node
__device__ float g_agg[(size_t)N_NODES * D];     // scatter-sum target
__device__ float g_B1[128 * 512];                // repacked node weights (fp32)
__device__ float g_stats[2 * D];                 // [sum | sumsq]
// B fragments for mma.sync m16n8k16 (bf16), fragment-linear:
// index = ((((term*8 + kstep)*32 + ntile)*32) + lane)*2 + reg   (uint32 slots)
// term 0 = hi, term 1 = lo. B logical: [k=128][n=256], n=2c -> Wf[256+k][c], n=2c+1 -> Ws[256+k][c]
__device__ __align__(16) uint32_t g_Bfrag[2 * 8 * 32 * 32 * 2];   // 128 KB

// ---------------- weight repack ----------------
__global__ void prep_weights(const float* __restrict__ Wf, const float* __restrict__ Ws) {
    int i = blockIdx.x * blockDim.x + threadIdx.x;
    if (i < 128 * 512) {
        int k = i >> 9, j = i & 511;
        float v;
        if (j < 128)      v = Wf[k * 128 + j];
        else if (j < 256) v = Wf[(128 + k) * 128 + (j - 128)];
        else if (j < 384) v = Ws[k * 128 + (j - 256)];
        else              v = Ws[(128 + k) * 128 + (j - 384)];
        g_B1[i] = v;
    }
    if (i < 32768) {
        int reg   = i & 1;
        int lane  = (i >> 1) & 31;
        int ntile = (i >> 6) & 31;
        int kstep = (i >> 11) & 7;
        int term  = (i >> 14) & 1;
        int k0 = kstep * 16 + (lane & 3) * 2 + reg * 8;
        int n  = ntile * 8 + (lane >> 2);
        int c  = n >> 1;
        const float* W = (n & 1) ? Ws : Wf;
        float v0 = W[(256 + k0) * 128 + c];
        float v1 = W[(256 + k0 + 1) * 128 + c];
        __nv_bfloat16 h0 = __float2bfloat16_rn(v0);
        __nv_bfloat16 h1 = __float2bfloat16_rn(v1);
        uint32_t out;
        if (term == 0) {
            out = (uint32_t)__bfloat16_as_ushort(h0) | ((uint32_t)__bfloat16_as_ushort(h1) << 16);
        } else {
            __nv_bfloat16 l0 = __float2bfloat16_rn(v0 - __bfloat162float(h0));
            __nv_bfloat16 l1 = __float2bfloat16_rn(v1 - __bfloat162float(h1));
            out = (uint32_t)__bfloat16_as_ushort(l0) | ((uint32_t)__bfloat16_as_ushort(l1) << 16);
        }
        g_Bfrag[i] = out;
    }
}

// ---------------- zero scratch ----------------
__global__ void zero_scratch() {
    size_t n4 = (size_t)N_NODES * D / 4;
    float4* p = reinterpret_cast<float4*>(g_agg);
    for (size_t i = blockIdx.x * blockDim.x + threadIdx.x; i < n4; i += (size_t)gridDim.x * blockDim.x)
        p[i] = make_float4(0.f, 0.f, 0.f, 0.f);
    int t = blockIdx.x * blockDim.x + threadIdx.x;
    if (t < 2 * D) g_stats[t] = 0.f;
}

// ---------------- node SGEMM: g_P[M,512] = x[M,128] @ g_B1[128,512] ----------------
#define BM 64
#define BN 64
#define BK 16
__global__ __launch_bounds__(256) void node_gemm(const float* __restrict__ A, int M)
{
    const float* __restrict__ B = g_B1;
    float* __restrict__ C = g_P;
    const int N = 512;
    __shared__ float As[BK][BM];
    __shared__ float Bs[BK][BN];
    const int tid = threadIdx.x;
    const int row0 = blockIdx.y * BM;
    const int col0 = blockIdx.x * BN;
    const int tr = tid >> 4, tc = tid & 15;
    const int a_r = tid >> 2, a_c4 = (tid & 3) * 4;
    const int b_r = tid >> 4, b_c4 = (tid & 15) * 4;
    float acc[4][4];
#pragma unroll
    for (int i = 0; i < 4; i++)
#pragma unroll
        for (int j = 0; j < 4; j++) acc[i][j] = 0.f;
    const int ar = row0 + a_r;
    for (int k0 = 0; k0 < 128; k0 += BK) {
        float4 av = make_float4(0.f, 0.f, 0.f, 0.f);
        if (ar < M) av = *reinterpret_cast<const float4*>(A + (size_t)ar * 128 + k0 + a_c4);
        As[a_c4 + 0][a_r] = av.x; As[a_c4 + 1][a_r] = av.y;
        As[a_c4 + 2][a_r] = av.z; As[a_c4 + 3][a_r] = av.w;
        float4 bv = *reinterpret_cast<const float4*>(B + (size_t)(k0 + b_r) * N + col0 + b_c4);
        *reinterpret_cast<float4*>(&Bs[b_r][b_c4]) = bv;
        __syncthreads();
#pragma unroll
        for (int k = 0; k < BK; k++) {
            float4 a = *reinterpret_cast<float4*>(&As[k][tr * 4]);
            float4 b = *reinterpret_cast<float4*>(&Bs[k][tc * 4]);
            acc[0][0] += a.x * b.x; acc[0][1] += a.x * b.y; acc[0][2] += a.x * b.z; acc[0][3] += a.x * b.w;
            acc[1][0] += a.y * b.x; acc[1][1] += a.y * b.y; acc[1][2] += a.y * b.z; acc[1][3] += a.y * b.w;
            acc[2][0] += a.z * b.x; acc[2][1] += a.z * b.y; acc[2][2] += a.z * b.z; acc[2][3] += a.z * b.w;
            acc[3][0] += a.w * b.x; acc[3][1] += a.w * b.y; acc[3][2] += a.w * b.z; acc[3][3] += a.w * b.w;
        }
        __syncthreads();
    }
#pragma unroll
    for (int i = 0; i < 4; i++) {
        int row = row0 + tr * 4 + i;
        if (row < M) {
            float4 v = make_float4(acc[i][0], acc[i][1], acc[i][2], acc[i][3]);
            *reinterpret_cast<float4*>(C + (size_t)row * N + col0 + tc * 4) = v;
        }
    }
}

// ---------------- activations ----------------
__device__ __forceinline__ float sigmoidf_(float x) { return 1.f / (1.f + expf(-x)); }
__device__ __forceinline__ float softplusf_(float x) {
    return fmaxf(x, 0.f) + log1pf(expf(-fabsf(x)));
}

__device__ __forceinline__ void mma_bf16(float* d, uint32_t a0, uint32_t a1, uint32_t a2,
                                         uint32_t a3, uint32_t b0, uint32_t b1) {
    asm volatile(
        "mma.sync.aligned.m16n8k16.row.col.f32.bf16.bf16.f32 "
        "{%0,%1,%2,%3}, {%4,%5,%6,%7}, {%8,%9}, {%0,%1,%2,%3};"
        : "+f"(d[0]), "+f"(d[1]), "+f"(d[2]), "+f"(d[3])
        : "r"(a0), "r"(a1), "r"(a2), "r"(a3), "r"(b0), "r"(b1));
}

// ---------------- fused edge GEMM (mma.sync bf16-split, smem-resident B) ----------------
// CTA: 512 threads, 128 edges x 256 interleaved cols (2c=f_c, 2c+1=s_c), K=128.
// Warps: 4M x 4N — warpM = wid&3 (32 rows), warpN = wid>>2 (64 interleaved cols).
// smem: [0,512) src, [512,1024) tgt,
//       A hi [1024, 35840) 128x272B,  A lo [35840, 70656),
//       B table [70656, 201728) = 128 KB fragment-linear copy of g_Bfrag.
//       D overlay at 1024: 128 x 260 fp32 (133120 B; overlays A + dead part of B).
#define SM_SRC 0
#define SM_TGT 512
#define SM_AHI 1024
#define SM_ALO (1024 + 128 * 272)
#define SM_B   (1024 + 2 * 128 * 272)
#define SM_D   1024
#define DSTRIDE 260
#define EDGE_SMEM (SM_B + 131072)

__global__ __launch_bounds__(512, 1) void edge_fused_mma(
    const float* __restrict__ A,
    const int* __restrict__ src, const int* __restrict__ tgt,
    const float* __restrict__ bf, const float* __restrict__ bs)
{
    extern __shared__ char basep[];
    const int tid = threadIdx.x;
    const int wid = tid >> 5;
    const int lane = tid & 31;
    const int row0 = blockIdx.x * 128;
    const int warpM = wid & 3;   // 0..3 (32 rows each)
    const int warpN = wid >> 2;  // 0..3 (64 interleaved cols each)

    int* s_src = reinterpret_cast<int*>(basep + SM_SRC);
    int* s_tgt = reinterpret_cast<int*>(basep + SM_TGT);
    if (tid < 128) {
        int r = row0 + tid;
        s_src[tid] = (r < N_EDGES) ? src[r] : 0;
        s_tgt[tid] = (r < N_EDGES) ? tgt[r] : 0;
    }

    // B table: global -> smem (once per CTA; 8192 int4 / 512 thr = 16 each)
    {
        int4* dst = reinterpret_cast<int4*>(basep + SM_B);
        const int4* s = reinterpret_cast<const int4*>(g_Bfrag);
#pragma unroll
        for (int i = 0; i < 16; i++) dst[i * 512 + tid] = s[i * 512 + tid];
    }

    // A tile: load 128x128 fp32, split bf16 hi/lo into smem (row stride 272 B)
    {
        char* ahi = basep + SM_AHI;
        char* alo = basep + SM_ALO;
#pragma unroll
        for (int it = 0; it < 8; it++) {
            int lin = it * 512 + tid;        // float4 over 128x32
            int row = lin >> 5;
            int c4 = (lin & 31) << 2;
            int e = row0 + row;
            float4 v = make_float4(0.f, 0.f, 0.f, 0.f);
            if (e < N_EDGES) v = *reinterpret_cast<const float4*>(A + (size_t)e * 128 + c4);
            __nv_bfloat16 h0 = __float2bfloat16_rn(v.x), h1 = __float2bfloat16_rn(v.y);
            __nv_bfloat16 h2 = __float2bfloat16_rn(v.z), h3 = __float2bfloat16_rn(v.w);
            __nv_bfloat16 l0 = __float2bfloat16_rn(v.x - __bfloat162float(h0));
            __nv_bfloat16 l1 = __float2bfloat16_rn(v.y - __bfloat162float(h1));
            __nv_bfloat16 l2 = __float2bfloat16_rn(v.z - __bfloat162float(h2));
            __nv_bfloat16 l3 = __float2bfloat16_rn(v.w - __bfloat162float(h3));
            uint2 hp, lp;
            hp.x = (uint32_t)__bfloat16_as_ushort(h0) | ((uint32_t)__bfloat16_as_ushort(h1) << 16);
            hp.y = (uint32_t)__bfloat16_as_ushort(h2) | ((uint32_t)__bfloat16_as_ushort(h3) << 16);
            lp.x = (uint32_t)__bfloat16_as_ushort(l0) | ((uint32_t)__bfloat16_as_ushort(l1) << 16);
            lp.y = (uint32_t)__bfloat16_as_ushort(l2) | ((uint32_t)__bfloat16_as_ushort(l3) << 16);
            int off = row * 272 + c4 * 2;
            *reinterpret_cast<uint2*>(ahi + off) = hp;
            *reinterpret_cast<uint2*>(alo + off) = lp;
        }
    }
    __syncthreads();

    float acc[2][8][4];
#pragma unroll
    for (int mt = 0; mt < 2; mt++)
#pragma unroll
        for (int nt = 0; nt < 8; nt++)
#pragma unroll
            for (int j = 0; j < 4; j++) acc[mt][nt][j] = 0.f;

    // mainloop: smem-fed, hi-frag reuse (Ahi*Bhi + Alo*Bhi + Ahi*Blo per nt)
    {
        const uint2* bp = reinterpret_cast<const uint2*>(basep + SM_B);
#pragma unroll
        for (int kstep = 0; kstep < 8; kstep++) {
            const int baseH = ((0 * 8 + kstep) * 32 + warpN * 8) * 32 + lane;
            const int baseL = ((1 * 8 + kstep) * 32 + warpN * 8) * 32 + lane;
#pragma unroll
            for (int mt = 0; mt < 2; mt++) {
                int arow = warpM * 32 + mt * 16 + (lane >> 2);
                int acolb = (kstep * 16 + (lane & 3) * 2) * 2;
                const char* aph = basep + SM_AHI + arow * 272 + acolb;
                const char* apl = basep + SM_ALO + arow * 272 + acolb;
                uint32_t ah0 = *reinterpret_cast<const uint32_t*>(aph);
                uint32_t ah1 = *reinterpret_cast<const uint32_t*>(aph + 8 * 272);
                uint32_t ah2 = *reinterpret_cast<const uint32_t*>(aph + 16);
                uint32_t ah3 = *reinterpret_cast<const uint32_t*>(aph + 8 * 272 + 16);
                uint32_t al0 = *reinterpret_cast<const uint32_t*>(apl);
                uint32_t al1 = *reinterpret_cast<const uint32_t*>(apl + 8 * 272);
                uint32_t al2 = *reinterpret_cast<const uint32_t*>(apl + 16);
                uint32_t al3 = *reinterpret_cast<const uint32_t*>(apl + 8 * 272 + 16);
#pragma unroll
                for (int nt = 0; nt < 8; nt++) {
                    uint2 bh = bp[baseH + nt * 32];
                    uint2 bl = bp[baseL + nt * 32];
                    mma_bf16(acc[mt][nt], ah0, ah1, ah2, ah3, bh.x, bh.y);
                    mma_bf16(acc[mt][nt], al0, al1, al2, al3, bh.x, bh.y);
                    mma_bf16(acc[mt][nt], ah0, ah1, ah2, ah3, bl.x, bl.y);
                }
            }
        }
    }
    __syncthreads();   // A + B regions dead; reuse as D staging

    // acc -> smem D [128][DSTRIDE]
    {
        float* Dsm = reinterpret_cast<float*>(basep + SM_D);
#pragma unroll
        for (int mt = 0; mt < 2; mt++) {
            int row = warpM * 32 + mt * 16 + (lane >> 2);
#pragma unroll
            for (int nt = 0; nt < 8; nt++) {
                int col = warpN * 64 + nt * 8 + (lane & 3) * 2;
                float* p0 = Dsm + (size_t)row * DSTRIDE + col;
                p0[0] = acc[mt][nt][0];
                p0[1] = acc[mt][nt][1];
                float* p1 = p0 + 8 * DSTRIDE;
                p1[0] = acc[mt][nt][2];
                p1[1] = acc[mt][nt][3];
            }
        }
    }
    __syncthreads();

    // epilogue: gate + scatter (cols interleaved: 2c=f_c, 2c+1=s_c)
    {
        const float* Dsm = reinterpret_cast<const float*>(basep + SM_D);
        const int tr = tid >> 5;   // 16 groups x 8 rows
        const int tc = tid & 31;   // orig cols tc*4..+3
        const float4 bfv = *reinterpret_cast<const float4*>(bf + tc * 4);
        const float4 bsv = *reinterpret_cast<const float4*>(bs + tc * 4);
#pragma unroll 4
        for (int i = 0; i < 8; i++) {
            int lr = tr * 8 + i;
            int e = row0 + lr;
            if (e >= N_EDGES) break;
            int sN = s_src[lr];
            int tN = s_tgt[lr];
            const float* dp = Dsm + (size_t)lr * DSTRIDE + tc * 8;
            float4 d0 = *reinterpret_cast<const float4*>(dp);       // f0,s0,f1,s1
            float4 d1 = *reinterpret_cast<const float4*>(dp + 4);   // f2,s2,f3,s3

            const float4 pf1 = *reinterpret_cast<const float4*>(g_P + (size_t)sN * 512 + 0   + tc * 4);
            const float4 pf2 = *reinterpret_cast<const float4*>(g_P + (size_t)tN * 512 + 128 + tc * 4);
            const float4 ps1 = *reinterpret_cast<const float4*>(g_P + (size_t)sN * 512 + 256 + tc * 4);
            const float4 ps2 = *reinterpret_cast<const float4*>(g_P + (size_t)tN * 512 + 384 + tc * 4);

            float f0 = d0.x + pf1.x + pf2.x + bfv.x;
            float s0 = d0.y + ps1.x + ps2.x + bsv.x;
            float f1 = d0.z + pf1.y + pf2.y + bfv.y;
            float s1 = d0.w + ps1.y + ps2.y + bsv.y;
            float f2 = d1.x + pf1.z + pf2.z + bfv.z;
            float s2 = d1.y + ps1.z + ps2.z + bsv.z;
            float f3 = d1.z + pf1.w + pf2.w + bfv.w;
            float s3 = d1.w + ps1.w + ps2.w + bsv.w;

            float m0 = sigmoidf_(f0) * softplusf_(s0);
            float m1 = sigmoidf_(f1) * softplusf_(s1);
            float m2 = sigmoidf_(f2) * softplusf_(s2);
            float m3 = sigmoidf_(f3) * softplusf_(s3);

            float* dst = g_agg + (size_t)sN * D + tc * 4;
            asm volatile("red.global.add.v4.f32 [%0], {%1, %2, %3, %4};"
                         :: "l"(dst), "f"(m0), "f"(m1), "f"(m2), "f"(m3) : "memory");
        }
    }
}

// ---------------- BN stats ----------------
__global__ __launch_bounds__(128) void bn_stats() {
    const int d = threadIdx.x;
    float sum = 0.f, sq = 0.f;
    for (int n = blockIdx.x; n < N_NODES; n += gridDim.x) {
        float v = g_agg[(size_t)n * D + d];
        sum += v;
        sq += v * v;
    }
    atomicAdd(&g_stats[d], sum);
    atomicAdd(&g_stats[D + d], sq);
}

// ---------------- BN apply + residual + softplus ----------------
__global__ __launch_bounds__(256) void final_kernel(
    const float* __restrict__ x, const float* __restrict__ gamma,
    const float* __restrict__ beta, float* __restrict__ out)
{
    const float invN = 1.0f / (float)N_NODES;
    for (size_t idx = (size_t)blockIdx.x * blockDim.x + threadIdx.x;
         idx < (size_t)N_NODES * D;
         idx += (size_t)gridDim.x * blockDim.x) {
        int d = (int)(idx & (D - 1));
        float mean = g_stats[d] * invN;
        float var = g_stats[D + d] * invN - mean * mean;
        float rstd = rsqrtf(var + BN_EPS);
        float a = (g_agg[idx] - mean) * rstd * gamma[d] + beta[d];
        out[idx] = softplusf_(x[idx] + a);
    }
}

// ---------------- launch ----------------
extern "C" void kernel_launch(void* const* d_in, const int* in_sizes, int n_in,
                              void* d_out, int out_size) {
    const float* x         = (const float*)d_in[0];
    const float* edge_attr = (const float*)d_in[1];
    const int*   edge_src  = (const int*)d_in[2];
    const int*   edge_tgt  = (const int*)d_in[3];
    const float* Wf        = (const float*)d_in[4];
    const float* bf        = (const float*)d_in[5];
    const float* Ws        = (const float*)d_in[6];
    const float* bs        = (const float*)d_in[7];
    const float* gamma     = (const float*)d_in[8];
    const float* beta      = (const float*)d_in[9];
    float* out = (float*)d_out;

    static bool attr_set = false;
    if (!attr_set) {
        cudaFuncSetAttribute(edge_fused_mma, cudaFuncAttributeMaxDynamicSharedMemorySize, EDGE_SMEM);
        attr_set = true;
    }

    prep_weights<<<256, 256>>>(Wf, Ws);
    zero_scratch<<<4096, 256>>>();
    {
        dim3 grid(512 / BN, (N_NODES + BM - 1) / BM);
        node_gemm<<<grid, 256>>>(x, N_NODES);
    }
    {
        int blocks = (N_EDGES + 127) / 128;
        edge_fused_mma<<<blocks, 512, EDGE_SMEM>>>(edge_attr, edge_src, edge_tgt, bf, bs);
    }
    bn_stats<<<512, 128>>>();
    final_kernel<<<(N_NODES * D + 255) / 256, 256>>>(x, gamma, beta, out);
}